// round 1
// baseline (speedup 1.0000x reference)
#include <cuda_runtime.h>

#define AA 64
#define NN 128
#define HH 8
#define GG 4
#define THREADS 256
#define OUTW (AA - 1)          // 63
#define OUT_PER (AA * OUTW)    // 4032 floats per (t,b) tile
#define OUT4_PER (OUT_PER / 4) // 1008 float4

// ---- packed f32x2 helpers (Blackwell FFMA2) ----
__device__ __forceinline__ unsigned long long pk2(float lo, float hi) {
    unsigned long long r;
    asm("mov.b64 %0, {%1, %2};" : "=l"(r) : "f"(lo), "f"(hi));
    return r;
}
__device__ __forceinline__ void upk2(unsigned long long v, float &lo, float &hi) {
    asm("mov.b64 {%0, %1}, %2;" : "=f"(lo), "=f"(hi) : "l"(v));
}
__device__ __forceinline__ void ffma2(unsigned long long &d,
                                      unsigned long long a,
                                      unsigned long long b) {
    asm("fma.rn.f32x2 %0, %1, %2, %0;" : "+l"(d) : "l"(a), "l"(b));
}

__global__ void __launch_bounds__(THREADS)
attn_kernel(const float* __restrict__ state,
            const float* __restrict__ Wq, const float* __restrict__ bq,
            const float* __restrict__ Wk, const float* __restrict__ bk,
            float* __restrict__ out)
{
    // weights packed: s_w[n*16 + 0..7] = Wq[n][0..7], s_w[n*16 + 8..15] = Wk[n][0..7]
    __shared__ __align__(16) float s_w[NN * 16];      // 8 KB
    __shared__ __align__(16) float s_q[GG * AA * HH]; // 8 KB
    __shared__ __align__(16) float s_k[GG * AA * HH]; // 8 KB
    __shared__ __align__(16) float s_att[AA * AA];    // 16 KB (reused per g)

    const int tid = threadIdx.x;
    const int blk = blockIdx.x;

    for (int i = tid; i < NN * HH; i += THREADS) {
        const int n = i >> 3, h = i & 7;
        s_w[n * 16 + h]     = Wq[i];
        s_w[n * 16 + 8 + h] = Wk[i];
    }

    const int row = tid >> 2;       // 0..63 : agent row within tile
    const int sub = tid & 3;        // 0..3  : selects (mat, h-half)
    const int hh  = (sub & 1) * 4;  // h offset within matrix

    // bias for this thread's 4 outputs (seed the accumulators with it)
    const float* bsel = (sub < 2) ? bq : bk;
    const float b0 = bsel[hh + 0], b1 = bsel[hh + 1];
    const float b2 = bsel[hh + 2], b3 = bsel[hh + 3];

    __syncthreads();

    // ---------------- Phase 1+2: fused load + Q/K projection -------------
    unsigned long long acc[GG][2];
    #pragma unroll
    for (int g = 0; g < GG; g++) { acc[g][0] = pk2(b0, b1); acc[g][1] = pk2(b2, b3); }

    const float4* sp0 =
        (const float4*)(state + ((size_t)(blk * GG) * AA + row) * NN);
    const ulonglong2* wp = (const ulonglong2*)s_w;  // [n*4 + sub] -> 4 floats

    #pragma unroll 4
    for (int i = 0; i < NN / 4; i++) {
        const ulonglong2 w0 = wp[(i * 4 + 0) * 4 + sub];
        const ulonglong2 w1 = wp[(i * 4 + 1) * 4 + sub];
        const ulonglong2 w2 = wp[(i * 4 + 2) * 4 + sub];
        const ulonglong2 w3 = wp[(i * 4 + 3) * 4 + sub];
        #pragma unroll
        for (int g = 0; g < GG; g++) {
            const float4 x = sp0[g * (AA * NN / 4) + i];
            unsigned long long xx;
            xx = pk2(x.x, x.x); ffma2(acc[g][0], xx, w0.x); ffma2(acc[g][1], xx, w0.y);
            xx = pk2(x.y, x.y); ffma2(acc[g][0], xx, w1.x); ffma2(acc[g][1], xx, w1.y);
            xx = pk2(x.z, x.z); ffma2(acc[g][0], xx, w2.x); ffma2(acc[g][1], xx, w2.y);
            xx = pk2(x.w, x.w); ffma2(acc[g][0], xx, w3.x); ffma2(acc[g][1], xx, w3.y);
        }
    }

    float* qk_dst = ((sub < 2) ? s_q : s_k) + row * HH + hh;
    #pragma unroll
    for (int g = 0; g < GG; g++) {
        float o0, o1, o2, o3;
        upk2(acc[g][0], o0, o1);
        upk2(acc[g][1], o2, o3);
        *(float4*)(qk_dst + g * (AA * HH)) = make_float4(o0, o1, o2, o3);
    }
    __syncthreads();

    // ------------- Phase 3-5 per tile: att, softmax, off-diag write ------
    const int jbase = sub * 16;
    for (int g = 0; g < GG; g++) {
        const float* qrow = s_q + g * (AA * HH) + row * HH;
        const float4 qa = *(const float4*)qrow;
        const float4 qb = *(const float4*)(qrow + 4);
        const float qr[8] = {qa.x, qa.y, qa.z, qa.w, qb.x, qb.y, qb.z, qb.w};

        unsigned long long at2[8];
        #pragma unroll
        for (int p = 0; p < 8; p++) at2[p] = 0ull;

        // reshape trick: kr[h][j] = k_flat[h*64 + j]
        const float* kg = s_k + g * (AA * HH);
        #pragma unroll
        for (int h = 0; h < HH; h++) {
            const unsigned long long qq = pk2(qr[h], qr[h]);
            const ulonglong2* kp = (const ulonglong2*)(kg + h * AA + jbase);
            const ulonglong2 k0 = kp[0], k1 = kp[1], k2 = kp[2], k3 = kp[3];
            ffma2(at2[0], qq, k0.x); ffma2(at2[1], qq, k0.y);
            ffma2(at2[2], qq, k1.x); ffma2(at2[3], qq, k1.y);
            ffma2(at2[4], qq, k2.x); ffma2(at2[5], qq, k2.y);
            ffma2(at2[6], qq, k3.x); ffma2(at2[7], qq, k3.y);
        }

        float a[16];
        #pragma unroll
        for (int p = 0; p < 8; p++) upk2(at2[p], a[2 * p], a[2 * p + 1]);

        float m = a[0];
        #pragma unroll
        for (int c = 1; c < 16; c++) m = fmaxf(m, a[c]);
        m = fmaxf(m, __shfl_xor_sync(0xffffffffu, m, 1));
        m = fmaxf(m, __shfl_xor_sync(0xffffffffu, m, 2));

        float s = 0.f;
        #pragma unroll
        for (int c = 0; c < 16; c++) { a[c] = __expf(a[c] - m); s += a[c]; }
        s += __shfl_xor_sync(0xffffffffu, s, 1);
        s += __shfl_xor_sync(0xffffffffu, s, 2);
        const float rinv = __frcp_rn(s);

        float4* arow = (float4*)(s_att + row * AA + jbase);
        arow[0] = make_float4(a[0]  * rinv, a[1]  * rinv, a[2]  * rinv, a[3]  * rinv);
        arow[1] = make_float4(a[4]  * rinv, a[5]  * rinv, a[6]  * rinv, a[7]  * rinv);
        arow[2] = make_float4(a[8]  * rinv, a[9]  * rinv, a[10] * rinv, a[11] * rinv);
        arow[3] = make_float4(a[12] * rinv, a[13] * rinv, a[14] * rinv, a[15] * rinv);
        __syncthreads();

        // coalesced float4 store of the 64x63 off-diagonal gather
        float4* o4p = (float4*)(out + (size_t)(blk * GG + g) * OUT_PER);
        #pragma unroll
        for (int it = 0; it < 4; it++) {
            const int o4 = it * THREADS + tid;
            if (o4 < OUT4_PER) {
                const unsigned o = (unsigned)o4 * 4u;
                float v[4];
                #pragma unroll
                for (int c = 0; c < 4; c++) {
                    const unsigned oc = o + c;
                    const unsigned rr = oc / OUTW;
                    const unsigned jj = oc - rr * OUTW;
                    const unsigned j  = jj + (jj >= rr ? 1u : 0u);
                    v[c] = s_att[rr * AA + j];
                }
                o4p[o4] = make_float4(v[0], v[1], v[2], v[3]);
            }
        }
        __syncthreads();
    }
}

extern "C" void kernel_launch(void* const* d_in, const int* in_sizes, int n_in,
                              void* d_out, int out_size) {
    const float* state = (const float*)d_in[0];
    const float* Wq    = (const float*)d_in[1];
    const float* bq    = (const float*)d_in[2];
    const float* Wk    = (const float*)d_in[3];
    const float* bk    = (const float*)d_in[4];
    float* out = (float*)d_out;

    const int tb = in_sizes[0] / (AA * NN);  // T*B = 16384
    attn_kernel<<<tb / GG, THREADS>>>(state, Wq, bq, Wk, bk, out);
}

// round 2
// speedup vs baseline: 1.0034x; 1.0034x over previous
#include <cuda_runtime.h>

#define AA 64
#define NN 128
#define HH 8
#define GG 4
#define THREADS 256
#define OUTW (AA - 1)          // 63
#define OUT_PER (AA * OUTW)    // 4032 floats per (t,b) tile
#define OUT4_PER (OUT_PER / 4) // 1008 float4

// ---- packed f32x2 helpers (Blackwell FFMA2) ----
__device__ __forceinline__ unsigned long long pk2(float lo, float hi) {
    unsigned long long r;
    asm("mov.b64 %0, {%1, %2};" : "=l"(r) : "f"(lo), "f"(hi));
    return r;
}
__device__ __forceinline__ void upk2(unsigned long long v, float &lo, float &hi) {
    asm("mov.b64 {%0, %1}, %2;" : "=f"(lo), "=f"(hi) : "l"(v));
}
__device__ __forceinline__ void ffma2(unsigned long long &d,
                                      unsigned long long a,
                                      unsigned long long b) {
    asm("fma.rn.f32x2 %0, %1, %2, %0;" : "+l"(d) : "l"(a), "l"(b));
}

__global__ void __launch_bounds__(THREADS)
attn_kernel(const float* __restrict__ state,
            const float* __restrict__ Wq, const float* __restrict__ bq,
            const float* __restrict__ Wk, const float* __restrict__ bk,
            float* __restrict__ out)
{
    // weights packed: s_w[n*16 + 0..7] = Wq[n][0..7], s_w[n*16 + 8..15] = Wk[n][0..7]
    __shared__ __align__(16) float s_w[NN * 16];      // 8 KB
    __shared__ __align__(16) float s_q[GG * AA * HH]; // 8 KB
    __shared__ __align__(16) float s_k[GG * AA * HH]; // 8 KB
    __shared__ __align__(16) float s_att[AA * AA];    // 16 KB (reused per g)

    const int tid = threadIdx.x;
    const int blk = blockIdx.x;

    for (int i = tid; i < NN * HH; i += THREADS) {
        const int n = i >> 3, h = i & 7;
        s_w[n * 16 + h]     = Wq[i];
        s_w[n * 16 + 8 + h] = Wk[i];
    }

    const int row = tid >> 2;       // 0..63 : agent row within tile
    const int sub = tid & 3;        // 0..3  : selects (mat, h-half)
    const int hh  = (sub & 1) * 4;  // h offset within matrix

    // bias for this thread's 4 outputs (seed the accumulators with it)
    const float* bsel = (sub < 2) ? bq : bk;
    const float b0 = bsel[hh + 0], b1 = bsel[hh + 1];
    const float b2 = bsel[hh + 2], b3 = bsel[hh + 3];

    __syncthreads();

    // ---------------- Phase 1+2: fused load + Q/K projection -------------
    unsigned long long acc[GG][2];
    #pragma unroll
    for (int g = 0; g < GG; g++) { acc[g][0] = pk2(b0, b1); acc[g][1] = pk2(b2, b3); }

    const float4* sp0 =
        (const float4*)(state + ((size_t)(blk * GG) * AA + row) * NN);
    const ulonglong2* wp = (const ulonglong2*)s_w;  // [n*4 + sub] -> 4 floats

    #pragma unroll 4
    for (int i = 0; i < NN / 4; i++) {
        const ulonglong2 w0 = wp[(i * 4 + 0) * 4 + sub];
        const ulonglong2 w1 = wp[(i * 4 + 1) * 4 + sub];
        const ulonglong2 w2 = wp[(i * 4 + 2) * 4 + sub];
        const ulonglong2 w3 = wp[(i * 4 + 3) * 4 + sub];
        #pragma unroll
        for (int g = 0; g < GG; g++) {
            const float4 x = sp0[g * (AA * NN / 4) + i];
            unsigned long long xx;
            xx = pk2(x.x, x.x); ffma2(acc[g][0], xx, w0.x); ffma2(acc[g][1], xx, w0.y);
            xx = pk2(x.y, x.y); ffma2(acc[g][0], xx, w1.x); ffma2(acc[g][1], xx, w1.y);
            xx = pk2(x.z, x.z); ffma2(acc[g][0], xx, w2.x); ffma2(acc[g][1], xx, w2.y);
            xx = pk2(x.w, x.w); ffma2(acc[g][0], xx, w3.x); ffma2(acc[g][1], xx, w3.y);
        }
    }

    float* qk_dst = ((sub < 2) ? s_q : s_k) + row * HH + hh;
    #pragma unroll
    for (int g = 0; g < GG; g++) {
        float o0, o1, o2, o3;
        upk2(acc[g][0], o0, o1);
        upk2(acc[g][1], o2, o3);
        *(float4*)(qk_dst + g * (AA * HH)) = make_float4(o0, o1, o2, o3);
    }
    __syncthreads();

    // ------------- Phase 3-5 per tile: att, softmax, off-diag write ------
    const int jbase = sub * 16;
    for (int g = 0; g < GG; g++) {
        const float* qrow = s_q + g * (AA * HH) + row * HH;
        const float4 qa = *(const float4*)qrow;
        const float4 qb = *(const float4*)(qrow + 4);
        const float qr[8] = {qa.x, qa.y, qa.z, qa.w, qb.x, qb.y, qb.z, qb.w};

        unsigned long long at2[8];
        #pragma unroll
        for (int p = 0; p < 8; p++) at2[p] = 0ull;

        // reshape trick: kr[h][j] = k_flat[h*64 + j]
        const float* kg = s_k + g * (AA * HH);
        #pragma unroll
        for (int h = 0; h < HH; h++) {
            const unsigned long long qq = pk2(qr[h], qr[h]);
            const ulonglong2* kp = (const ulonglong2*)(kg + h * AA + jbase);
            const ulonglong2 k0 = kp[0], k1 = kp[1], k2 = kp[2], k3 = kp[3];
            ffma2(at2[0], qq, k0.x); ffma2(at2[1], qq, k0.y);
            ffma2(at2[2], qq, k1.x); ffma2(at2[3], qq, k1.y);
            ffma2(at2[4], qq, k2.x); ffma2(at2[5], qq, k2.y);
            ffma2(at2[6], qq, k3.x); ffma2(at2[7], qq, k3.y);
        }

        float a[16];
        #pragma unroll
        for (int p = 0; p < 8; p++) upk2(at2[p], a[2 * p], a[2 * p + 1]);

        float m = a[0];
        #pragma unroll
        for (int c = 1; c < 16; c++) m = fmaxf(m, a[c]);
        m = fmaxf(m, __shfl_xor_sync(0xffffffffu, m, 1));
        m = fmaxf(m, __shfl_xor_sync(0xffffffffu, m, 2));

        float s = 0.f;
        #pragma unroll
        for (int c = 0; c < 16; c++) { a[c] = __expf(a[c] - m); s += a[c]; }
        s += __shfl_xor_sync(0xffffffffu, s, 1);
        s += __shfl_xor_sync(0xffffffffu, s, 2);
        const float rinv = __frcp_rn(s);

        float4* arow = (float4*)(s_att + row * AA + jbase);
        arow[0] = make_float4(a[0]  * rinv, a[1]  * rinv, a[2]  * rinv, a[3]  * rinv);
        arow[1] = make_float4(a[4]  * rinv, a[5]  * rinv, a[6]  * rinv, a[7]  * rinv);
        arow[2] = make_float4(a[8]  * rinv, a[9]  * rinv, a[10] * rinv, a[11] * rinv);
        arow[3] = make_float4(a[12] * rinv, a[13] * rinv, a[14] * rinv, a[15] * rinv);
        __syncthreads();

        // coalesced float4 store of the 64x63 off-diagonal gather
        float4* o4p = (float4*)(out + (size_t)(blk * GG + g) * OUT_PER);
        #pragma unroll
        for (int it = 0; it < 4; it++) {
            const int o4 = it * THREADS + tid;
            if (o4 < OUT4_PER) {
                const unsigned o = (unsigned)o4 * 4u;
                float v[4];
                #pragma unroll
                for (int c = 0; c < 4; c++) {
                    const unsigned oc = o + c;
                    const unsigned rr = oc / OUTW;
                    const unsigned jj = oc - rr * OUTW;
                    const unsigned j  = jj + (jj >= rr ? 1u : 0u);
                    v[c] = s_att[rr * AA + j];
                }
                o4p[o4] = make_float4(v[0], v[1], v[2], v[3]);
            }
        }
        __syncthreads();
    }
}

extern "C" void kernel_launch(void* const* d_in, const int* in_sizes, int n_in,
                              void* d_out, int out_size) {
    const float* state = (const float*)d_in[0];
    const float* Wq    = (const float*)d_in[1];
    const float* bq    = (const float*)d_in[2];
    const float* Wk    = (const float*)d_in[3];
    const float* bk    = (const float*)d_in[4];
    float* out = (float*)d_out;

    const int tb = in_sizes[0] / (AA * NN);  // T*B = 16384
    attn_kernel<<<tb / GG, THREADS>>>(state, Wq, bq, Wk, bk, out);
}